// round 1
// baseline (speedup 1.0000x reference)
#include <cuda_runtime.h>
#include <math.h>

#define Nn 16384
#define Mm 8192
#define Dd 512
#define Ff 2048

// ---------------- scratch (device globals; no allocation allowed) ----------
__device__ float g_anorm[Mm];
__device__ int   g_idx[Nn * 5];
__device__ float g_neigh[(size_t)Nn * Dd];
__device__ float g_amap [(size_t)Nn * Dd];
__device__ float g_comb [(size_t)Nn * Dd];
__device__ float g_h    [(size_t)Nn * Ff];
__device__ float g_comb2[(size_t)Nn * Dd];
__device__ float g_z    [(size_t)Nn * Dd];
__device__ float g_part [2 * 64 * Dd];
__device__ float g_mean [Dd];
__device__ float g_rstd [Dd];

// ---------------- anchor squared norms ----------------
__global__ void anchor_norm_kernel(const float* __restrict__ anc) {
    int warp = (blockIdx.x * blockDim.x + threadIdx.x) >> 5;
    int lane = threadIdx.x & 31;
    if (warp >= Mm) return;
    const float* a = anc + (size_t)warp * Dd;
    float s = 0.f;
    #pragma unroll 4
    for (int i = lane; i < Dd; i += 32) { float v = a[i]; s += v * v; }
    #pragma unroll
    for (int o = 16; o; o >>= 1) s += __shfl_xor_sync(0xffffffffu, s, o);
    if (!lane) g_anorm[warp] = s;
}

// ---------------- fused distance GEMM + per-row top-5 ----------------
// Block: 128 src rows. Loops over 64 anchor tiles of 128; for each tile
// computes the 128x128 score matrix (register-tiled fp32 GEMM) and updates
// a per-row top-5 kept in the registers of thread (tid == row-within-block).
__global__ void __launch_bounds__(256) knn_kernel(const float* __restrict__ src,
                                                  const float* __restrict__ anc) {
    extern __shared__ float sm[];
    float* Xs = sm;               // [16][128] transposed src tile
    float* Ws = sm + 16 * 128;    // [16][128] transposed anchor tile
    float* S  = sm + 32 * 128;    // [128][129] score tile

    const int tid = threadIdx.x;
    const int tx = tid & 15, ty = tid >> 4;
    const int row0 = blockIdx.x * 128;
    const int lr = tid >> 2;          // 0..63
    const int lk = (tid & 3) * 4;     // 0,4,8,12

    float bv0 = 3.4e38f, bv1 = 3.4e38f, bv2 = 3.4e38f, bv3 = 3.4e38f, bv4 = 3.4e38f;
    int   bi0 = 0, bi1 = 0, bi2 = 0, bi3 = 0, bi4 = 0;

    for (int jt = 0; jt < Mm / 128; jt++) {
        float acc[8][8];
        #pragma unroll
        for (int i = 0; i < 8; i++)
            #pragma unroll
            for (int j = 0; j < 8; j++) acc[i][j] = 0.f;

        for (int kt = 0; kt < Dd; kt += 16) {
            #pragma unroll
            for (int h = 0; h < 2; h++) {
                int r = lr + h * 64;
                float4 v = *(const float4*)(src + (size_t)(row0 + r) * Dd + kt + lk);
                Xs[(lk + 0) * 128 + r] = v.x; Xs[(lk + 1) * 128 + r] = v.y;
                Xs[(lk + 2) * 128 + r] = v.z; Xs[(lk + 3) * 128 + r] = v.w;
            }
            #pragma unroll
            for (int h = 0; h < 2; h++) {
                int r = lr + h * 64;
                float4 v = *(const float4*)(anc + (size_t)(jt * 128 + r) * Dd + kt + lk);
                Ws[(lk + 0) * 128 + r] = v.x; Ws[(lk + 1) * 128 + r] = v.y;
                Ws[(lk + 2) * 128 + r] = v.z; Ws[(lk + 3) * 128 + r] = v.w;
            }
            __syncthreads();
            #pragma unroll
            for (int k = 0; k < 16; k++) {
                float4 a0 = *(const float4*)(Xs + k * 128 + ty * 8);
                float4 a1 = *(const float4*)(Xs + k * 128 + ty * 8 + 4);
                float4 b0 = *(const float4*)(Ws + k * 128 + tx * 8);
                float4 b1 = *(const float4*)(Ws + k * 128 + tx * 8 + 4);
                float ar[8] = {a0.x, a0.y, a0.z, a0.w, a1.x, a1.y, a1.z, a1.w};
                float br[8] = {b0.x, b0.y, b0.z, b0.w, b1.x, b1.y, b1.z, b1.w};
                #pragma unroll
                for (int i = 0; i < 8; i++)
                    #pragma unroll
                    for (int j = 0; j < 8; j++)
                        acc[i][j] += ar[i] * br[j];
            }
            __syncthreads();
        }

        // scores: ||a||^2 - 2 * dot  (|s|^2 is a per-row constant; order-preserving)
        float anv[8];
        #pragma unroll
        for (int j = 0; j < 8; j++) anv[j] = g_anorm[jt * 128 + tx * 8 + j];
        #pragma unroll
        for (int i = 0; i < 8; i++)
            #pragma unroll
            for (int j = 0; j < 8; j++)
                S[(ty * 8 + i) * 129 + tx * 8 + j] = anv[j] - 2.f * acc[i][j];
        __syncthreads();

        if (tid < 128) {
            #pragma unroll 4
            for (int c = 0; c < 128; c++) {
                float s = S[tid * 129 + c];
                if (s < bv4) {
                    int m = jt * 128 + c;
                    if (s < bv3) {
                        bv4 = bv3; bi4 = bi3;
                        if (s < bv2) {
                            bv3 = bv2; bi3 = bi2;
                            if (s < bv1) {
                                bv2 = bv1; bi2 = bi1;
                                if (s < bv0) { bv1 = bv0; bi1 = bi0; bv0 = s; bi0 = m; }
                                else { bv1 = s; bi1 = m; }
                            } else { bv2 = s; bi2 = m; }
                        } else { bv3 = s; bi3 = m; }
                    } else { bv4 = s; bi4 = m; }
                }
            }
        }
        __syncthreads();
    }
    if (tid < 128) {
        int* o = &g_idx[(size_t)(row0 + tid) * 5];
        o[0] = bi0; o[1] = bi1; o[2] = bi2; o[3] = bi3; o[4] = bi4;
    }
}

// ---------------- gather + mean of 5 anchor rows ----------------
__global__ void neigh_mean_kernel(const float* __restrict__ anc) {
    int n = blockIdx.x;
    int d = threadIdx.x;  // 128 float4 lanes cover 512 cols
    const int* id = &g_idx[(size_t)n * 5];
    float4 a = ((const float4*)(anc + (size_t)id[0] * Dd))[d];
    float4 b = ((const float4*)(anc + (size_t)id[1] * Dd))[d];
    float4 c = ((const float4*)(anc + (size_t)id[2] * Dd))[d];
    float4 e = ((const float4*)(anc + (size_t)id[3] * Dd))[d];
    float4 f = ((const float4*)(anc + (size_t)id[4] * Dd))[d];
    float4 o;
    o.x = (a.x + b.x + c.x + e.x + f.x) * 0.2f;
    o.y = (a.y + b.y + c.y + e.y + f.y) * 0.2f;
    o.z = (a.z + b.z + c.z + e.z + f.z) * 0.2f;
    o.w = (a.w + b.w + c.w + e.w + f.w) * 0.2f;
    ((float4*)(g_neigh + (size_t)n * Dd))[d] = o;
}

// ---------------- generic fp32 GEMM: C = A[MxK] @ B[KxN] (+epilogues) ------
// flags: 1 = accumulate into existing C, 2 = tanh epilogue
__global__ void __launch_bounds__(256) gemm_kernel(
    const float* __restrict__ A, const float* __restrict__ B,
    const float* __restrict__ bias, const float* __restrict__ res,
    float* __restrict__ C, int M, int N, int K, int flags) {
    __shared__ float As[16 * 128];
    __shared__ float Bs[16 * 128];
    const int tid = threadIdx.x;
    const int tx = tid & 15, ty = tid >> 4;
    const int row0 = blockIdx.y * 128, col0 = blockIdx.x * 128;
    const int lr = tid >> 2, lk = (tid & 3) * 4;
    const int bkr = tid >> 5, bc = (tid & 31) * 4;
    float acc[8][8];
    #pragma unroll
    for (int i = 0; i < 8; i++)
        #pragma unroll
        for (int j = 0; j < 8; j++) acc[i][j] = 0.f;

    for (int kt = 0; kt < K; kt += 16) {
        #pragma unroll
        for (int h = 0; h < 2; h++) {
            int r = lr + h * 64;
            float4 v = *(const float4*)(A + (size_t)(row0 + r) * K + kt + lk);
            As[(lk + 0) * 128 + r] = v.x; As[(lk + 1) * 128 + r] = v.y;
            As[(lk + 2) * 128 + r] = v.z; As[(lk + 3) * 128 + r] = v.w;
        }
        #pragma unroll
        for (int h = 0; h < 2; h++) {
            int kr = bkr + h * 8;
            float4 v = *(const float4*)(B + (size_t)(kt + kr) * N + col0 + bc);
            *(float4*)(Bs + kr * 128 + bc) = v;
        }
        __syncthreads();
        #pragma unroll
        for (int k = 0; k < 16; k++) {
            float4 a0 = *(const float4*)(As + k * 128 + ty * 8);
            float4 a1 = *(const float4*)(As + k * 128 + ty * 8 + 4);
            float4 b0 = *(const float4*)(Bs + k * 128 + tx * 8);
            float4 b1 = *(const float4*)(Bs + k * 128 + tx * 8 + 4);
            float ar[8] = {a0.x, a0.y, a0.z, a0.w, a1.x, a1.y, a1.z, a1.w};
            float br[8] = {b0.x, b0.y, b0.z, b0.w, b1.x, b1.y, b1.z, b1.w};
            #pragma unroll
            for (int i = 0; i < 8; i++)
                #pragma unroll
                for (int j = 0; j < 8; j++)
                    acc[i][j] += ar[i] * br[j];
        }
        __syncthreads();
    }
    #pragma unroll
    for (int i = 0; i < 8; i++) {
        int r = row0 + ty * 8 + i;
        #pragma unroll
        for (int j = 0; j < 8; j++) {
            int c = col0 + tx * 8 + j;
            float v = acc[i][j];
            if (flags & 1) v += C[(size_t)r * N + c];
            if (bias) v += bias[c];
            if (res)  v += res[(size_t)r * N + c];
            if (flags & 2) v = tanhf(v);
            C[(size_t)r * N + c] = v;
        }
    }
}

// ---------------- batch-norm (training-mode batch stats over N) ------------
__global__ void bn_stats_kernel(const float* __restrict__ x) {
    int d = threadIdx.x;                 // 512 threads = columns
    int b = blockIdx.x;                  // 64 blocks of 256 rows
    int r0 = b * (Nn / 64);
    float s = 0.f, s2 = 0.f;
    for (int r = r0; r < r0 + Nn / 64; r++) {
        float v = x[(size_t)r * Dd + d];
        s += v; s2 += v * v;
    }
    g_part[b * Dd + d] = s;
    g_part[64 * Dd + b * Dd + d] = s2;
}

__global__ void bn_finalize_kernel() {
    int d = threadIdx.x;                 // 512
    float s = 0.f, s2 = 0.f;
    for (int b = 0; b < 64; b++) {
        s  += g_part[b * Dd + d];
        s2 += g_part[64 * Dd + b * Dd + d];
    }
    float mu = s * (1.f / Nn);
    float var = s2 * (1.f / Nn) - mu * mu;
    g_mean[d] = mu;
    g_rstd[d] = rsqrtf(var + 1e-5f);
}

__global__ void bn_apply_kernel(const float* __restrict__ x, float* __restrict__ y,
                                const float* __restrict__ g, const float* __restrict__ b,
                                int dotanh) {
    size_t i4 = ((size_t)blockIdx.x * blockDim.x + threadIdx.x) * 4;
    int c = (int)(i4 & (Dd - 1));
    float4 v = *(const float4*)(x + i4);
    float o0 = (v.x - g_mean[c + 0]) * g_rstd[c + 0] * g[c + 0] + b[c + 0];
    float o1 = (v.y - g_mean[c + 1]) * g_rstd[c + 1] * g[c + 1] + b[c + 1];
    float o2 = (v.z - g_mean[c + 2]) * g_rstd[c + 2] * g[c + 2] + b[c + 2];
    float o3 = (v.w - g_mean[c + 3]) * g_rstd[c + 3] * g[c + 3] + b[c + 3];
    if (dotanh) { o0 = tanhf(o0); o1 = tanhf(o1); o2 = tanhf(o2); o3 = tanhf(o3); }
    *(float4*)(y + i4) = make_float4(o0, o1, o2, o3);
}

// ---------------- host orchestration ----------------
static void bn_block(const float* x, float* y, const float* g, const float* b, int dotanh) {
    bn_stats_kernel<<<64, 512>>>(x);
    bn_finalize_kernel<<<1, 512>>>();
    bn_apply_kernel<<<(Nn * Dd / 4) / 256, 256>>>(x, y, g, b, dotanh);
}

extern "C" void kernel_launch(void* const* d_in, const int* in_sizes, int n_in,
                              void* d_out, int out_size) {
    const float* src   = (const float*)d_in[0];
    const float* anc   = (const float*)d_in[1];
    const float* W_dim = (const float*)d_in[2];
    const float* b_dim = (const float*)d_in[3];
    const float* W_fus = (const float*)d_in[4];
    const float* b_fus = (const float*)d_in[5];
    const float* W_e1  = (const float*)d_in[6];
    const float* b_e1  = (const float*)d_in[7];
    const float* W_e2  = (const float*)d_in[8];
    const float* b_e2  = (const float*)d_in[9];
    const float* g1    = (const float*)d_in[10];
    const float* bt1   = (const float*)d_in[11];
    const float* g2    = (const float*)d_in[12];
    const float* bt2   = (const float*)d_in[13];
    const float* W_d   = (const float*)d_in[14];
    const float* b_d   = (const float*)d_in[15];
    const float* g_d   = (const float*)d_in[16];
    const float* bt_d  = (const float*)d_in[17];
    float* out = (float*)d_out;

    float *p_neigh, *p_amap, *p_comb, *p_h, *p_comb2, *p_z;
    cudaGetSymbolAddress((void**)&p_neigh, g_neigh);
    cudaGetSymbolAddress((void**)&p_amap,  g_amap);
    cudaGetSymbolAddress((void**)&p_comb,  g_comb);
    cudaGetSymbolAddress((void**)&p_h,     g_h);
    cudaGetSymbolAddress((void**)&p_comb2, g_comb2);
    cudaGetSymbolAddress((void**)&p_z,     g_z);

    // 1) anchor norms + kNN top-5 + neighbor mean
    anchor_norm_kernel<<<Mm / 8, 256>>>(anc);
    size_t knn_smem = (size_t)(32 * 128 + 128 * 129) * sizeof(float);
    cudaFuncSetAttribute(knn_kernel, cudaFuncAttributeMaxDynamicSharedMemorySize,
                         (int)knn_smem);
    knn_kernel<<<Nn / 128, 256, knn_smem>>>(src, anc);
    neigh_mean_kernel<<<Nn, 128>>>(anc);

    // 2) a_map = neigh @ W_dim + b_dim
    gemm_kernel<<<dim3(Dd / 128, Nn / 128), 256>>>(p_neigh, W_dim, b_dim, nullptr,
                                                   p_amap, Nn, Dd, Dd, 0);

    // 3) comb = [src, a_map] @ W_fus + b_fus (split as two K=512 GEMMs)
    gemm_kernel<<<dim3(Dd / 128, Nn / 128), 256>>>(src, W_fus, nullptr, nullptr,
                                                   p_comb, Nn, Dd, Dd, 0);
    gemm_kernel<<<dim3(Dd / 128, Nn / 128), 256>>>(p_amap, W_fus + (size_t)Dd * Dd,
                                                   b_fus, nullptr, p_comb, Nn, Dd, Dd, 1);

    // 4) norm1 (in place)
    bn_block(p_comb, p_comb, g1, bt1, 0);

    // 5) encoder: h = tanh(comb @ W_e1 + b_e1); comb2 = h @ W_e2 + b_e2 + comb
    gemm_kernel<<<dim3(Ff / 128, Nn / 128), 256>>>(p_comb, W_e1, b_e1, nullptr,
                                                   p_h, Nn, Ff, Dd, 2);
    gemm_kernel<<<dim3(Dd / 128, Nn / 128), 256>>>(p_h, W_e2, b_e2, p_comb,
                                                   p_comb2, Nn, Dd, Ff, 0);

    // 6) norm2 (in place)
    bn_block(p_comb2, p_comb2, g2, bt2, 0);

    // 7) decoder: out = tanh(bn(comb2 @ W_d + b_d))
    gemm_kernel<<<dim3(Dd / 128, Nn / 128), 256>>>(p_comb2, W_d, b_d, nullptr,
                                                   p_z, Nn, Dd, Dd, 0);
    bn_block(p_z, out, g_d, bt_d, 1);
}

// round 7
// speedup vs baseline: 1.3043x; 1.3043x over previous
#include <cuda_runtime.h>
#include <cuda_bf16.h>
#include <cstdint>
#include <math.h>

#define Nn 16384
#define Mm 8192
#define Dd 512
#define Ff 2048
#define KC 32

// ===================== low-level helpers (arch-portable PTX) ============
__device__ __forceinline__ uint32_t smem_u32(const void* p) {
    uint32_t a;
    asm("{ .reg .u64 t; cvta.to.shared.u64 t, %1; cvt.u32.u64 %0, t; }"
        : "=r"(a) : "l"(p));
    return a;
}
#define SWZ64(o) ((o) ^ (((o) >> 3) & 0x30))

__device__ __forceinline__ void cp_async16(uint32_t s, const void* g) {
    asm volatile("cp.async.cg.shared.global [%0], [%1], 16;" :: "r"(s), "l"(g));
}
#define CP_COMMIT() asm volatile("cp.async.commit_group;" ::: "memory")
#define CP_WAIT1()  asm volatile("cp.async.wait_group 1;" ::: "memory")
#define CP_WAIT0()  asm volatile("cp.async.wait_group 0;" ::: "memory")

__device__ __forceinline__ void ldsm4(uint32_t* r, uint32_t a) {
    asm volatile("ldmatrix.sync.aligned.m8n8.x4.shared.b16 {%0,%1,%2,%3}, [%4];"
                 : "=r"(r[0]), "=r"(r[1]), "=r"(r[2]), "=r"(r[3]) : "r"(a));
}
__device__ __forceinline__ void mma16816(float* c, const uint32_t* a, const uint32_t* b) {
    asm volatile("mma.sync.aligned.m16n8k16.row.col.f32.bf16.bf16.f32 "
                 "{%0,%1,%2,%3}, {%4,%5,%6,%7}, {%8,%9}, {%0,%1,%2,%3};"
                 : "+f"(c[0]), "+f"(c[1]), "+f"(c[2]), "+f"(c[3])
                 : "r"(a[0]), "r"(a[1]), "r"(a[2]), "r"(a[3]), "r"(b[0]), "r"(b[1]));
}

// ===================== device scratch =====================
__device__ float g_anorm[Mm];
__device__ int   g_idx[Nn * 5];
__device__ float g_neigh[(size_t)Nn * Dd];

__device__ __nv_bfloat16 g_src_h[(size_t)Nn * Dd], g_src_l[(size_t)Nn * Dd];
__device__ __nv_bfloat16 g_neigh_h[(size_t)Nn * Dd], g_neigh_l[(size_t)Nn * Dd];
__device__ __nv_bfloat16 g_amap_h[(size_t)Nn * Dd],  g_amap_l[(size_t)Nn * Dd];
__device__ __nv_bfloat16 g_comb_h[(size_t)Nn * Dd],  g_comb_l[(size_t)Nn * Dd];
__device__ __nv_bfloat16 g_hid_h[(size_t)Nn * Ff],   g_hid_l[(size_t)Nn * Ff];
__device__ __nv_bfloat16 g_comb2_h[(size_t)Nn * Dd], g_comb2_l[(size_t)Nn * Dd];

__device__ __nv_bfloat16 g_Wdim_h[Dd * Dd], g_Wdim_l[Dd * Dd];
__device__ __nv_bfloat16 g_Wf1_h[Dd * Dd],  g_Wf1_l[Dd * Dd];
__device__ __nv_bfloat16 g_Wf2_h[Dd * Dd],  g_Wf2_l[Dd * Dd];
__device__ __nv_bfloat16 g_We1_h[Ff * Dd],  g_We1_l[Ff * Dd];   // [N=2048, K=512]
__device__ __nv_bfloat16 g_We2_h[Dd * Ff],  g_We2_l[Dd * Ff];   // [N=512,  K=2048]
__device__ __nv_bfloat16 g_Wd_h[Dd * Dd],   g_Wd_l[Dd * Dd];

__device__ float g_amap_f [(size_t)Nn * Dd];
__device__ float g_comb_f [(size_t)Nn * Dd];
__device__ float g_hid_f  [(size_t)Nn * Ff];
__device__ float g_comb2_f[(size_t)Nn * Dd];
__device__ float g_z_f    [(size_t)Nn * Dd];
__device__ float g_part[2 * 64 * Dd];
__device__ float g_mean[Dd];
__device__ float g_rstd[Dd];

// ===================== anchor squared norms (R1, proven) ================
__global__ void anchor_norm_kernel(const float* __restrict__ anc) {
    int warp = (blockIdx.x * blockDim.x + threadIdx.x) >> 5;
    int lane = threadIdx.x & 31;
    if (warp >= Mm) return;
    const float* a = anc + (size_t)warp * Dd;
    float s = 0.f;
    #pragma unroll 4
    for (int i = lane; i < Dd; i += 32) { float v = a[i]; s += v * v; }
    #pragma unroll
    for (int o = 16; o; o >>= 1) s += __shfl_xor_sync(0xffffffffu, s, o);
    if (!lane) g_anorm[warp] = s;
}

// ========== exact fp32 distance GEMM + per-row top-5 (R1, proven) ========
__global__ void __launch_bounds__(256) knn_kernel(const float* __restrict__ src,
                                                  const float* __restrict__ anc) {
    extern __shared__ float sm[];
    float* Xs = sm;               // [16][128] transposed src tile
    float* Ws = sm + 16 * 128;    // [16][128] transposed anchor tile
    float* S  = sm + 32 * 128;    // [128][129] score tile

    const int tid = threadIdx.x;
    const int tx = tid & 15, ty = tid >> 4;
    const int row0 = blockIdx.x * 128;
    const int lr = tid >> 2;          // 0..63
    const int lk = (tid & 3) * 4;     // 0,4,8,12

    float bv0 = 3.4e38f, bv1 = 3.4e38f, bv2 = 3.4e38f, bv3 = 3.4e38f, bv4 = 3.4e38f;
    int   bi0 = 0, bi1 = 0, bi2 = 0, bi3 = 0, bi4 = 0;

    for (int jt = 0; jt < Mm / 128; jt++) {
        float acc[8][8];
        #pragma unroll
        for (int i = 0; i < 8; i++)
            #pragma unroll
            for (int j = 0; j < 8; j++) acc[i][j] = 0.f;

        for (int kt = 0; kt < Dd; kt += 16) {
            #pragma unroll
            for (int h = 0; h < 2; h++) {
                int r = lr + h * 64;
                float4 v = *(const float4*)(src + (size_t)(row0 + r) * Dd + kt + lk);
                Xs[(lk + 0) * 128 + r] = v.x; Xs[(lk + 1) * 128 + r] = v.y;
                Xs[(lk + 2) * 128 + r] = v.z; Xs[(lk + 3) * 128 + r] = v.w;
            }
            #pragma unroll
            for (int h = 0; h < 2; h++) {
                int r = lr + h * 64;
                float4 v = *(const float4*)(anc + (size_t)(jt * 128 + r) * Dd + kt + lk);
                Ws[(lk + 0) * 128 + r] = v.x; Ws[(lk + 1) * 128 + r] = v.y;
                Ws[(lk + 2) * 128 + r] = v.z; Ws[(lk + 3) * 128 + r] = v.w;
            }
            __syncthreads();
            #pragma unroll
            for (int k = 0; k < 16; k++) {
                float4 a0 = *(const float4*)(Xs + k * 128 + ty * 8);
                float4 a1 = *(const float4*)(Xs + k * 128 + ty * 8 + 4);
                float4 b0 = *(const float4*)(Ws + k * 128 + tx * 8);
                float4 b1 = *(const float4*)(Ws + k * 128 + tx * 8 + 4);
                float ar[8] = {a0.x, a0.y, a0.z, a0.w, a1.x, a1.y, a1.z, a1.w};
                float br[8] = {b0.x, b0.y, b0.z, b0.w, b1.x, b1.y, b1.z, b1.w};
                #pragma unroll
                for (int i = 0; i < 8; i++)
                    #pragma unroll
                    for (int j = 0; j < 8; j++)
                        acc[i][j] += ar[i] * br[j];
            }
            __syncthreads();
        }

        float anv[8];
        #pragma unroll
        for (int j = 0; j < 8; j++) anv[j] = g_anorm[jt * 128 + tx * 8 + j];
        #pragma unroll
        for (int i = 0; i < 8; i++)
            #pragma unroll
            for (int j = 0; j < 8; j++)
                S[(ty * 8 + i) * 129 + tx * 8 + j] = anv[j] - 2.f * acc[i][j];
        __syncthreads();

        if (tid < 128) {
            #pragma unroll 4
            for (int c = 0; c < 128; c++) {
                float s = S[tid * 129 + c];
                if (s < bv4) {
                    int m = jt * 128 + c;
                    if (s < bv3) {
                        bv4 = bv3; bi4 = bi3;
                        if (s < bv2) {
                            bv3 = bv2; bi3 = bi2;
                            if (s < bv1) {
                                bv2 = bv1; bi2 = bi1;
                                if (s < bv0) { bv1 = bv0; bi1 = bi0; bv0 = s; bi0 = m; }
                                else { bv1 = s; bi1 = m; }
                            } else { bv2 = s; bi2 = m; }
                        } else { bv3 = s; bi3 = m; }
                    } else { bv4 = s; bi4 = m; }
                }
            }
        }
        __syncthreads();
    }
    if (tid < 128) {
        int* o = &g_idx[(size_t)(row0 + tid) * 5];
        o[0] = bi0; o[1] = bi1; o[2] = bi2; o[3] = bi3; o[4] = bi4;
    }
}

// ============ gather + mean of 5 anchor rows (R1, proven) ================
__global__ void neigh_mean_kernel(const float* __restrict__ anc) {
    int n = blockIdx.x;
    int d = threadIdx.x;  // 128 float4 lanes cover 512 cols
    const int* id = &g_idx[(size_t)n * 5];
    float4 a = ((const float4*)(anc + (size_t)id[0] * Dd))[d];
    float4 b = ((const float4*)(anc + (size_t)id[1] * Dd))[d];
    float4 c = ((const float4*)(anc + (size_t)id[2] * Dd))[d];
    float4 e = ((const float4*)(anc + (size_t)id[3] * Dd))[d];
    float4 f = ((const float4*)(anc + (size_t)id[4] * Dd))[d];
    float4 o;
    o.x = (a.x + b.x + c.x + e.x + f.x) * 0.2f;
    o.y = (a.y + b.y + c.y + e.y + f.y) * 0.2f;
    o.z = (a.z + b.z + c.z + e.z + f.z) * 0.2f;
    o.w = (a.w + b.w + c.w + e.w + f.w) * 0.2f;
    ((float4*)(g_neigh + (size_t)n * Dd))[d] = o;
}

// ===================== small conversion kernels =====================
__global__ void split_kernel(const float* __restrict__ x, __nv_bfloat16* __restrict__ h,
                             __nv_bfloat16* __restrict__ l, int n4) {
    int i = blockIdx.x * blockDim.x + threadIdx.x;
    if (i >= n4) return;
    float4 v = ((const float4*)x)[i];
    __nv_bfloat16 h0 = __float2bfloat16(v.x), h1 = __float2bfloat16(v.y);
    __nv_bfloat16 h2 = __float2bfloat16(v.z), h3 = __float2bfloat16(v.w);
    __nv_bfloat16 l0 = __float2bfloat16(v.x - __bfloat162float(h0));
    __nv_bfloat16 l1 = __float2bfloat16(v.y - __bfloat162float(h1));
    __nv_bfloat16 l2 = __float2bfloat16(v.z - __bfloat162float(h2));
    __nv_bfloat16 l3 = __float2bfloat16(v.w - __bfloat162float(h3));
    __nv_bfloat162 a; a.x = h0; a.y = h1;
    __nv_bfloat162 b; b.x = h2; b.y = h3;
    ((__nv_bfloat162*)h)[2 * i] = a; ((__nv_bfloat162*)h)[2 * i + 1] = b;
    a.x = l0; a.y = l1; b.x = l2; b.y = l3;
    ((__nv_bfloat162*)l)[2 * i] = a; ((__nv_bfloat162*)l)[2 * i + 1] = b;
}

// transpose + split: W [Kd, Nd] fp32 -> th/tl [Nd, Kd] bf16
__global__ void wt_split_kernel(const float* __restrict__ W, __nv_bfloat16* __restrict__ th,
                                __nv_bfloat16* __restrict__ tl, int Kd, int Nd) {
    __shared__ float tile[32][33];
    int kb = blockIdx.y * 32, nb = blockIdx.x * 32;
    int tx = threadIdx.x, ty = threadIdx.y;   // (32, 8)
    #pragma unroll
    for (int q = 0; q < 32; q += 8)
        tile[ty + q][tx] = W[(size_t)(kb + ty + q) * Nd + nb + tx];
    __syncthreads();
    #pragma unroll
    for (int q = 0; q < 32; q += 8) {
        float v = tile[tx][ty + q];
        __nv_bfloat16 h = __float2bfloat16(v);
        __nv_bfloat16 l = __float2bfloat16(v - __bfloat162float(h));
        size_t o = (size_t)(nb + ty + q) * Kd + kb + tx;
        th[o] = h; tl[o] = l;
    }
}

// ===================== shared GEMM pieces =====================
struct Seg { const __nv_bfloat16* A; const __nv_bfloat16* B; };
struct GArgs { Seg s[6]; int nseg; int K; };

// stage layout: A at stage*16384, B at +8192 (each 128 rows x 32 bf16, SW64)
__device__ __forceinline__ void load_stage(char* sm, int stage,
        const __nv_bfloat16* Ag, const __nv_bfloat16* Bg, int K,
        int row0, int col0, int kb, int tid) {
    uint32_t sA = smem_u32(sm) + (uint32_t)stage * 16384u;
    uint32_t sB = sA + 8192u;
    #pragma unroll
    for (int h = 0; h < 2; h++) {
        int c = tid + h * 256;
        int r = c >> 2, k4 = c & 3;
        uint32_t so = SWZ64(r * 64 + k4 * 16);
        cp_async16(sA + so, Ag + (size_t)(row0 + r) * K + kb + k4 * 8);
        cp_async16(sB + so, Bg + (size_t)(col0 + r) * K + kb + k4 * 8);
    }
}

// ============ dense GEMM: C[M,N] = sum_seg A@B^T (+bias,+res,tanh) =======
// warps 4(M) x 2(N); warp tile 32x64; mode 1 => tanh
__global__ void __launch_bounds__(256) mma_gemm_kernel(
        GArgs ga, int N, const float* __restrict__ bias,
        const float* __restrict__ res, float* __restrict__ C, int mode) {
    __shared__ __align__(128) char sm[32768];
    const int tid = threadIdx.x, lane = tid & 31, wid = tid >> 5;
    const int row0 = blockIdx.y * 128, col0 = blockIdx.x * 128;
    const int wm = (wid & 3) * 32, wn = (wid >> 2) * 64;
    const int cps = ga.K >> 5;
    const int nch = ga.nseg * cps;

    for (int c = 0; c < 2; c++) {
        int sg = c / cps, kb = (c % cps) * KC;
        load_stage(sm, c & 1, ga.s[sg].A, ga.s[sg].B, ga.K, row0, col0, kb, tid);
        CP_COMMIT();
    }

    float acc[2][8][4] = {};
    const uint32_t sbase = smem_u32(sm);
    const int a_rb = wm + (lane & 7) + ((lane & 8) ? 8 : 0);
    const int a_kf = (lane & 16) ? 8 : 0;
    const int b_rb = wn + (lane & 7) + ((lane & 16) ? 8 : 0);
    const int b_kf = (lane & 8) ? 8 : 0;

    for (int c = 0; c < nch; c++) {
        CP_WAIT1();
        __syncthreads();
        uint32_t sA = sbase + (uint32_t)(c & 1) * 16384u, sB = sA + 8192u;
        #pragma unroll
        for (int ks = 0; ks < 2; ks++) {
            uint32_t af[2][4];
            #pragma unroll
            for (int mt = 0; mt < 2; mt++)
                ldsm4(af[mt], sA + SWZ64((a_rb + mt * 16) * 64 + (ks * 16 + a_kf) * 2));
            uint32_t bf[8][2];
            #pragma unroll
            for (int p = 0; p < 4; p++) {
                uint32_t t[4];
                ldsm4(t, sB + SWZ64((b_rb + p * 16) * 64 + (ks * 16 + b_kf) * 2));
                bf[2 * p][0] = t[0]; bf[2 * p][1] = t[1];
                bf[2 * p + 1][0] = t[2]; bf[2 * p + 1][1] = t[3];
            }
            #pragma unroll
            for (int mt = 0; mt < 2; mt++)
                #pragma unroll
                for (int nt = 0; nt < 8; nt++)
                    mma16816(acc[mt][nt], af[mt], bf[nt]);
        }
        __syncthreads();
        int c2 = c + 2;
        if (c2 < nch) {
            int sg = c2 / cps, kb = (c2 % cps) * KC;
            load_stage(sm, c2 & 1, ga.s[sg].A, ga.s[sg].B, ga.K, row0, col0, kb, tid);
        }
        CP_COMMIT();
    }

    const int g = lane >> 2, u = lane & 3;
    #pragma unroll
    for (int mt = 0; mt < 2; mt++) {
        int r0 = row0 + wm + mt * 16 + g;
        #pragma unroll
        for (int nt = 0; nt < 8; nt++) {
            int cc = col0 + wn + nt * 8 + 2 * u;
            float b0 = 0.f, b1 = 0.f;
            if (bias) { float2 bb = *(const float2*)(bias + cc); b0 = bb.x; b1 = bb.y; }
            float v0 = acc[mt][nt][0] + b0, v1 = acc[mt][nt][1] + b1;
            float v2 = acc[mt][nt][2] + b0, v3 = acc[mt][nt][3] + b1;
            if (res) {
                float2 ra = *(const float2*)(res + (size_t)r0 * N + cc);
                float2 rb = *(const float2*)(res + (size_t)(r0 + 8) * N + cc);
                v0 += ra.x; v1 += ra.y; v2 += rb.x; v3 += rb.y;
            }
            if (mode == 1) { v0 = tanhf(v0); v1 = tanhf(v1); v2 = tanhf(v2); v3 = tanhf(v3); }
            *(float2*)(C + (size_t)r0 * N + cc) = make_float2(v0, v1);
            *(float2*)(C + (size_t)(r0 + 8) * N + cc) = make_float2(v2, v3);
        }
    }
}

// ===================== batch-norm (fp32) =====================
__global__ void bn_stats_kernel(const float* __restrict__ x) {
    int d = threadIdx.x;
    int b = blockIdx.x;
    int r0 = b * (Nn / 64);
    float s = 0.f, s2 = 0.f;
    for (int r = r0; r < r0 + Nn / 64; r++) {
        float v = x[(size_t)r * Dd + d];
        s += v; s2 += v * v;
    }
    g_part[b * Dd + d] = s;
    g_part[64 * Dd + b * Dd + d] = s2;
}
__global__ void bn_finalize_kernel() {
    int d = threadIdx.x;
    float s = 0.f, s2 = 0.f;
    for (int b = 0; b < 64; b++) {
        s  += g_part[b * Dd + d];
        s2 += g_part[64 * Dd + b * Dd + d];
    }
    float mu = s * (1.f / Nn);
    float var = s2 * (1.f / Nn) - mu * mu;
    g_mean[d] = mu;
    g_rstd[d] = rsqrtf(var + 1e-5f);
}
__global__ void bn_apply_kernel(const float* __restrict__ x, float* __restrict__ y,
                                const float* __restrict__ g, const float* __restrict__ b,
                                int dotanh) {
    size_t i4 = ((size_t)blockIdx.x * blockDim.x + threadIdx.x) * 4;
    int c = (int)(i4 & (Dd - 1));
    float4 v = *(const float4*)(x + i4);
    float o0 = (v.x - g_mean[c + 0]) * g_rstd[c + 0] * g[c + 0] + b[c + 0];
    float o1 = (v.y - g_mean[c + 1]) * g_rstd[c + 1] * g[c + 1] + b[c + 1];
    float o2 = (v.z - g_mean[c + 2]) * g_rstd[c + 2] * g[c + 2] + b[c + 2];
    float o3 = (v.w - g_mean[c + 3]) * g_rstd[c + 3] * g[c + 3] + b[c + 3];
    if (dotanh) { o0 = tanhf(o0); o1 = tanhf(o1); o2 = tanhf(o2); o3 = tanhf(o3); }
    *(float4*)(y + i4) = make_float4(o0, o1, o2, o3);
}

// ===================== host orchestration =====================
#define SYM(p, s) cudaGetSymbolAddress((void**)&(p), s)

static void bn_block(const float* x, float* y, const float* g, const float* b, int dotanh) {
    bn_stats_kernel<<<64, 512>>>(x);
    bn_finalize_kernel<<<1, 512>>>();
    bn_apply_kernel<<<(Nn * Dd / 4) / 256, 256>>>(x, y, g, b, dotanh);
}

extern "C" void kernel_launch(void* const* d_in, const int* in_sizes, int n_in,
                              void* d_out, int out_size) {
    const float* src   = (const float*)d_in[0];
    const float* anc   = (const float*)d_in[1];
    const float* W_dim = (const float*)d_in[2];
    const float* b_dim = (const float*)d_in[3];
    const float* W_fus = (const float*)d_in[4];
    const float* b_fus = (const float*)d_in[5];
    const float* W_e1  = (const float*)d_in[6];
    const float* b_e1  = (const float*)d_in[7];
    const float* W_e2  = (const float*)d_in[8];
    const float* b_e2  = (const float*)d_in[9];
    const float* g1    = (const float*)d_in[10];
    const float* bt1   = (const float*)d_in[11];
    const float* g2    = (const float*)d_in[12];
    const float* bt2   = (const float*)d_in[13];
    const float* W_d   = (const float*)d_in[14];
    const float* b_d   = (const float*)d_in[15];
    const float* g_dd  = (const float*)d_in[16];
    const float* bt_d  = (const float*)d_in[17];
    float* out = (float*)d_out;

    __nv_bfloat16 *p_src_h, *p_src_l, *p_neigh_h, *p_neigh_l;
    __nv_bfloat16 *p_amap_h, *p_amap_l, *p_comb_h, *p_comb_l, *p_hid_h, *p_hid_l;
    __nv_bfloat16 *p_comb2_h, *p_comb2_l;
    __nv_bfloat16 *p_Wdim_h, *p_Wdim_l, *p_Wf1_h, *p_Wf1_l, *p_Wf2_h, *p_Wf2_l;
    __nv_bfloat16 *p_We1_h, *p_We1_l, *p_We2_h, *p_We2_l, *p_Wd_h, *p_Wd_l;
    float *p_neigh, *p_amap_f, *p_comb_f, *p_hid_f, *p_comb2_f, *p_z_f;

    SYM(p_src_h, g_src_h);   SYM(p_src_l, g_src_l);
    SYM(p_neigh, g_neigh);
    SYM(p_neigh_h, g_neigh_h); SYM(p_neigh_l, g_neigh_l);
    SYM(p_amap_h, g_amap_h); SYM(p_amap_l, g_amap_l);
    SYM(p_comb_h, g_comb_h); SYM(p_comb_l, g_comb_l);
    SYM(p_hid_h, g_hid_h);   SYM(p_hid_l, g_hid_l);
    SYM(p_comb2_h, g_comb2_h); SYM(p_comb2_l, g_comb2_l);
    SYM(p_Wdim_h, g_Wdim_h); SYM(p_Wdim_l, g_Wdim_l);
    SYM(p_Wf1_h, g_Wf1_h);   SYM(p_Wf1_l, g_Wf1_l);
    SYM(p_Wf2_h, g_Wf2_h);   SYM(p_Wf2_l, g_Wf2_l);
    SYM(p_We1_h, g_We1_h);   SYM(p_We1_l, g_We1_l);
    SYM(p_We2_h, g_We2_h);   SYM(p_We2_l, g_We2_l);
    SYM(p_Wd_h, g_Wd_h);     SYM(p_Wd_l, g_Wd_l);
    SYM(p_amap_f, g_amap_f); SYM(p_comb_f, g_comb_f); SYM(p_hid_f, g_hid_f);
    SYM(p_comb2_f, g_comb2_f); SYM(p_z_f, g_z_f);

    // ---- exact fp32 kNN (R1-proven path) ----
    anchor_norm_kernel<<<Mm / 8, 256>>>(anc);
    size_t knn_smem = (size_t)(32 * 128 + 128 * 129) * sizeof(float);
    cudaFuncSetAttribute(knn_kernel, cudaFuncAttributeMaxDynamicSharedMemorySize,
                         (int)knn_smem);
    knn_kernel<<<Nn / 128, 256, knn_smem>>>(src, anc);
    neigh_mean_kernel<<<Nn, 128>>>(anc);

    // ---- conversions ----
    split_kernel<<<(Nn * Dd / 4) / 256, 256>>>(src, p_src_h, p_src_l, Nn * Dd / 4);
    split_kernel<<<(Nn * Dd / 4) / 256, 256>>>(p_neigh, p_neigh_h, p_neigh_l, Nn * Dd / 4);
    dim3 wtb(32, 8);
    wt_split_kernel<<<dim3(Dd / 32, Dd / 32), wtb>>>(W_dim, p_Wdim_h, p_Wdim_l, Dd, Dd);
    wt_split_kernel<<<dim3(Dd / 32, Dd / 32), wtb>>>(W_fus, p_Wf1_h, p_Wf1_l, Dd, Dd);
    wt_split_kernel<<<dim3(Dd / 32, Dd / 32), wtb>>>(W_fus + (size_t)Dd * Dd, p_Wf2_h, p_Wf2_l, Dd, Dd);
    wt_split_kernel<<<dim3(Ff / 32, Dd / 32), wtb>>>(W_e1, p_We1_h, p_We1_l, Dd, Ff);
    wt_split_kernel<<<dim3(Dd / 32, Ff / 32), wtb>>>(W_e2, p_We2_h, p_We2_l, Ff, Dd);
    wt_split_kernel<<<dim3(Dd / 32, Dd / 32), wtb>>>(W_d, p_Wd_h, p_Wd_l, Dd, Dd);

    // ---- a_map = neigh @ W_dim + b_dim ----
    {
        GArgs ga; ga.nseg = 3; ga.K = Dd;
        ga.s[0] = { p_neigh_h, p_Wdim_h };
        ga.s[1] = { p_neigh_l, p_Wdim_h };
        ga.s[2] = { p_neigh_h, p_Wdim_l };
        mma_gemm_kernel<<<dim3(Dd / 128, Nn / 128), 256>>>(ga, Dd, b_dim, nullptr, p_amap_f, 0);
    }
    split_kernel<<<(Nn * Dd / 4) / 256, 256>>>(p_amap_f, p_amap_h, p_amap_l, Nn * Dd / 4);

    // ---- comb = [src, a_map] @ W_fus + b_fus ----
    {
        GArgs ga; ga.nseg = 6; ga.K = Dd;
        ga.s[0] = { p_src_h,  p_Wf1_h };
        ga.s[1] = { p_src_l,  p_Wf1_h };
        ga.s[2] = { p_src_h,  p_Wf1_l };
        ga.s[3] = { p_amap_h, p_Wf2_h };
        ga.s[4] = { p_amap_l, p_Wf2_h };
        ga.s[5] = { p_amap_h, p_Wf2_l };
        mma_gemm_kernel<<<dim3(Dd / 128, Nn / 128), 256>>>(ga, Dd, b_fus, nullptr, p_comb_f, 0);
    }
    bn_block(p_comb_f, p_comb_f, g1, bt1, 0);
    split_kernel<<<(Nn * Dd / 4) / 256, 256>>>(p_comb_f, p_comb_h, p_comb_l, Nn * Dd / 4);

    // ---- h = tanh(comb @ W_e1 + b_e1) ----
    {
        GArgs ga; ga.nseg = 3; ga.K = Dd;
        ga.s[0] = { p_comb_h, p_We1_h };
        ga.s[1] = { p_comb_l, p_We1_h };
        ga.s[2] = { p_comb_h, p_We1_l };
        mma_gemm_kernel<<<dim3(Ff / 128, Nn / 128), 256>>>(ga, Ff, b_e1, nullptr, p_hid_f, 1);
    }
    split_kernel<<<(Nn * Ff / 4) / 256, 256>>>(p_hid_f, p_hid_h, p_hid_l, Nn * Ff / 4);

    // ---- comb2 = h @ W_e2 + b_e2 + comb ----
    {
        GArgs ga; ga.nseg = 3; ga.K = Ff;
        ga.s[0] = { p_hid_h, p_We2_h };
        ga.s[1] = { p_hid_l, p_We2_h };
        ga.s[2] = { p_hid_h, p_We2_l };
        mma_gemm_kernel<<<dim3(Dd / 128, Nn / 128), 256>>>(ga, Dd, b_e2, p_comb_f, p_comb2_f, 0);
    }
    bn_block(p_comb2_f, p_comb2_f, g2, bt2, 0);
    split_kernel<<<(Nn * Dd / 4) / 256, 256>>>(p_comb2_f, p_comb2_h, p_comb2_l, Nn * Dd / 4);

    // ---- z = comb2 @ W_d + b_d;  out = tanh(bn(z)) ----
    {
        GArgs ga; ga.nseg = 3; ga.K = Dd;
        ga.s[0] = { p_comb2_h, p_Wd_h };
        ga.s[1] = { p_comb2_l, p_Wd_h };
        ga.s[2] = { p_comb2_h, p_Wd_l };
        mma_gemm_kernel<<<dim3(Dd / 128, Nn / 128), 256>>>(ga, Dd, b_d, nullptr, p_z_f, 0);
    }
    bn_block(p_z_f, out, g_dd, bt_d, 1);
}